// round 7
// baseline (speedup 1.0000x reference)
#include <cuda_runtime.h>
#include <math.h>

#define KC 16
#define DD 64
#define NMAX 204800

// Precomputed per-component data: W = L^{-1} (lower-tri), t = W*mu,
// c = log(pi) - 0.5*D*log(2pi) - sum(log(diag(L)))
__device__ float g_W[KC][DD][DD];
__device__ float g_t[KC][DD];
__device__ float g_c[KC];
__device__ float g_logits[KC][NMAX];   // [K][N] scratch, coalesced writes

// ---------------- packed f32x2 helpers ----------------
__device__ __forceinline__ unsigned long long fma2(unsigned long long a,
                                                   unsigned long long b,
                                                   unsigned long long c) {
    unsigned long long d;
    asm("fma.rn.f32x2 %0, %1, %2, %3;" : "=l"(d) : "l"(a), "l"(b), "l"(c));
    return d;
}
__device__ __forceinline__ unsigned long long add2(unsigned long long a,
                                                   unsigned long long b) {
    unsigned long long d;
    asm("add.rn.f32x2 %0, %1, %2;" : "=l"(d) : "l"(a), "l"(b));
    return d;
}
__device__ __forceinline__ unsigned long long pk2(float lo, float hi) {
    unsigned long long r;
    asm("mov.b64 %0, {%1, %2};" : "=l"(r) : "f"(lo), "f"(hi));
    return r;
}
__device__ __forceinline__ float2 unpk2(unsigned long long v) {
    unsigned int lo, hi;
    asm("mov.b64 {%0, %1}, %2;" : "=r"(lo), "=r"(hi) : "l"(v));
    float2 f;
    f.x = __uint_as_float(lo);
    f.y = __uint_as_float(hi);
    return f;
}

// ---------------- cp.async helpers ----------------
__device__ __forceinline__ unsigned smem_u32(const void* p) {
    return (unsigned)__cvta_generic_to_shared(p);
}
__device__ __forceinline__ void cp16(unsigned dst, const void* src) {
    asm volatile("cp.async.cg.shared.global [%0], [%1], 16;\n"
                 :: "r"(dst), "l"(src));
}
__device__ __forceinline__ void cp_commit() {
    asm volatile("cp.async.commit_group;\n");
}
template <int N> __device__ __forceinline__ void cp_wait() {
    asm volatile("cp.async.wait_group %0;\n" :: "n"(N));
}

// ---------------- precompute v4: row-in-registers, static loops ----------
// (proven in R6: 33 us)
__global__ void __launch_bounds__(64)
gmm_precompute_kernel(const float* __restrict__ pi,
                      const float* __restrict__ mus,
                      const float* __restrict__ covs) {
    __shared__ float colbuf[2][DD];    // published column (double-buffered)
    __shared__ float rinv[DD];         // 1/L[j][j]
    __shared__ float Ls[DD][DD + 1];   // L (lower), read-only in phase 2
    __shared__ float Wsm[DD][DD + 1];  // W rows for t computation
    __shared__ float mu_s[DD];
    __shared__ float lg[DD];

    const int k = blockIdx.x;
    const int r = threadIdx.x;  // 0..63

    float a[DD];
    {
        const float4* src = (const float4*)(covs + ((size_t)k * DD + r) * DD);
#pragma unroll
        for (int i = 0; i < DD / 4; i++) {
            float4 v = src[i];
            a[4 * i] = v.x; a[4 * i + 1] = v.y;
            a[4 * i + 2] = v.z; a[4 * i + 3] = v.w;
        }
    }
    mu_s[r] = mus[k * DD + r];

    float lrow[DD];
    float d_own = 1.0f;
#pragma unroll
    for (int j = 0; j < DD; j++) {
        colbuf[j & 1][r] = a[j];
        __syncthreads();
        const float dj = colbuf[j & 1][j];
        const float rs = rsqrtf(dj);
        const float invd = rs * rs;
        lrow[j] = a[j] * rs;
        if (r == j) d_own = dj;
        const float s = a[j] * invd;
        if (r > j) {
#pragma unroll
            for (int q = j + 1; q < DD; q++)
                a[q] = fmaf(-s, colbuf[j & 1][q], a[q]);
        }
    }

    rinv[r] = rsqrtf(d_own);
    lg[r] = logf(d_own);
#pragma unroll
    for (int j = 0; j < DD; j++)
        Ls[r][j] = (r >= j) ? lrow[j] : 0.0f;
    __syncthreads();

    float w[DD];
#pragma unroll
    for (int i = 0; i < DD; i++)
        w[i] = (i == r) ? rinv[r] : 0.0f;
#pragma unroll
    for (int i = 1; i < DD; i++) {
        float acc = 0.0f;
#pragma unroll
        for (int j = 0; j < i; j++)
            acc = fmaf(Ls[i][j], w[j], acc);
        if (i > r) w[i] = -acc * rinv[i];
    }

#pragma unroll
    for (int i = 0; i < DD; i++) {
        g_W[k][i][r] = w[i];
        Wsm[i][r] = w[i];
    }
    __syncthreads();

    {
        float s = 0.0f;
#pragma unroll
        for (int j = 0; j < DD; j++)
            s = fmaf(Wsm[r][j], mu_s[j], s);
        g_t[k][r] = s;
    }
    if (r == 0) {
        float sl = 0.0f;
#pragma unroll
        for (int i = 0; i < DD; i++) sl += lg[i];
        g_c[k] = logf(pi[k]) - 32.0f * 1.8378770664093453f - 0.5f * sl;
    }
}

// ---------------- main kernel ----------------
// 256 threads/block, TWO points per thread, triangular matvec, 2 CTAs/SM
// -> 16 warps/SM (4/SMSP) for better latency hiding.
__global__ __launch_bounds__(256, 2)
void gmm_main_kernel(const float* __restrict__ X, int n) {
    __shared__ __align__(16) float Ws[2][DD * DD];  // 2 x 16 KB
    __shared__ __align__(16) float ts[2][DD];
    __shared__ float cs[KC];

    const int tid = threadIdx.x;
    const int p0 = (blockIdx.x * 256 + tid) * 2;
    const int ld0 = (p0 < n) ? p0 : (n - 1);
    const int ld1 = (p0 + 1 < n) ? (p0 + 1) : (n - 1);

    if (tid < KC) cs[tid] = g_c[tid];

    // Load both points into packed f32x2 registers (j-packing)
    unsigned long long pxA[DD / 2], pxB[DD / 2];
    {
        const float4* xr0 = (const float4*)(X + (size_t)ld0 * DD);
        const float4* xr1 = (const float4*)(X + (size_t)ld1 * DD);
#pragma unroll
        for (int i = 0; i < DD / 4; i++) {
            float4 v = xr0[i];
            pxA[2 * i]     = pk2(v.x, v.y);
            pxA[2 * i + 1] = pk2(v.z, v.w);
            float4 u = xr1[i];
            pxB[2 * i]     = pk2(u.x, u.y);
            pxB[2 * i + 1] = pk2(u.z, u.w);
        }
    }

    // prefetch component 0 into buffer 0 (1024 16B chunks / 256 threads)
    {
        const float4* src = (const float4*)&g_W[0][0][0];
        unsigned dst = smem_u32(&Ws[0][0]);
#pragma unroll
        for (int i = 0; i < 4; i++)
            cp16(dst + (unsigned)(tid + 256 * i) * 16, src + tid + 256 * i);
        if (tid < DD / 4)
            cp16(smem_u32(&ts[0][0]) + (unsigned)tid * 16,
                 ((const float4*)&g_t[0][0]) + tid);
        cp_commit();
    }

#pragma unroll 1
    for (int k = 0; k < KC; k++) {
        const int cur = k & 1;
        if (k < KC - 1) {
            const int nxt = (k + 1) & 1;
            const float4* src = (const float4*)&g_W[k + 1][0][0];
            unsigned dst = smem_u32(&Ws[nxt][0]);
#pragma unroll
            for (int i = 0; i < 4; i++)
                cp16(dst + (unsigned)(tid + 256 * i) * 16, src + tid + 256 * i);
            if (tid < DD / 4)
                cp16(smem_u32(&ts[nxt][0]) + (unsigned)tid * 16,
                     ((const float4*)&g_t[k + 1][0]) + tid);
            cp_commit();
            cp_wait<1>();
        } else {
            cp_wait<0>();
        }
        __syncthreads();

        const float* Wc = Ws[cur];
        const float* tc = ts[cur];

        float mahaA = 0.0f, mahaB = 0.0f;
        // rows grouped by 4; group g needs cols [0, 4g+4) — triangular W
#pragma unroll
        for (int g = 0; g < DD / 4; g++) {
#pragma unroll
            for (int r = 0; r < 4; r++) {
                const int i = 4 * g + r;
                unsigned long long a0 = 0ull, a1 = 0ull;
                unsigned long long b0 = 0ull, b1 = 0ull;
                const ulonglong2* wr = (const ulonglong2*)(Wc + i * DD);
#pragma unroll
                for (int j = 0; j <= g; j++) {
                    ulonglong2 w2 = wr[j];
                    a0 = fma2(w2.x, pxA[2 * j], a0);
                    a1 = fma2(w2.y, pxA[2 * j + 1], a1);
                    b0 = fma2(w2.x, pxB[2 * j], b0);
                    b1 = fma2(w2.y, pxB[2 * j + 1], b1);
                }
                const float ti = tc[i];
                float2 a = unpk2(add2(a0, a1));
                float da = (a.x + a.y) - ti;
                mahaA = fmaf(da, da, mahaA);
                float2 b = unpk2(add2(b0, b1));
                float db = (b.x + b.y) - ti;
                mahaB = fmaf(db, db, mahaB);
            }
        }
        if (p0 < n) {
            float2 lw = make_float2(cs[k] - 0.5f * mahaA,
                                    cs[k] - 0.5f * mahaB);
            if (p0 + 1 < n) {
                *(float2*)&g_logits[k][p0] = lw;
            } else {
                g_logits[k][p0] = lw.x;
            }
        }
        __syncthreads();
    }
}

// ---------------- softmax pass ----------------
__global__ __launch_bounds__(256)
void gmm_softmax_kernel(float* __restrict__ out, int n) {
    const int p = blockIdx.x * 256 + threadIdx.x;
    if (p >= n) return;
    float w[KC];
    float m = -INFINITY;
#pragma unroll
    for (int k = 0; k < KC; k++) {
        w[k] = g_logits[k][p];
        m = fmaxf(m, w[k]);
    }
    float s = 0.0f;
#pragma unroll
    for (int k = 0; k < KC; k++) {
        w[k] = __expf(w[k] - m);
        s += w[k];
    }
    const float inv = 1.0f / s;
    float4* orow = (float4*)(out + (size_t)p * KC);
#pragma unroll
    for (int q = 0; q < KC / 4; q++)
        orow[q] = make_float4(w[4 * q] * inv, w[4 * q + 1] * inv,
                              w[4 * q + 2] * inv, w[4 * q + 3] * inv);
}

extern "C" void kernel_launch(void* const* d_in, const int* in_sizes, int n_in,
                              void* d_out, int out_size) {
    const float* X    = (const float*)d_in[0];  // [N, 64]
    const float* pi   = (const float*)d_in[1];  // [16]
    const float* mus  = (const float*)d_in[2];  // [16, 64]
    const float* covs = (const float*)d_in[3];  // [16, 64, 64]
    float* out = (float*)d_out;                 // [N, 16]

    const int n = in_sizes[0] / DD;

    gmm_precompute_kernel<<<KC, DD>>>(pi, mus, covs);
    const int pts_per_block = 512;  // 256 threads x 2 points
    gmm_main_kernel<<<(n + pts_per_block - 1) / pts_per_block, 256>>>(X, n);
    gmm_softmax_kernel<<<(n + 255) / 256, 256>>>(out, n);
}

// round 8
// speedup vs baseline: 1.3834x; 1.3834x over previous
#include <cuda_runtime.h>
#include <math.h>

#define KC 16
#define DD 64

// Precomputed per-component data: W = L^{-1} (lower-tri), t = W*mu,
// c = log(pi) - 0.5*D*log(2pi) - sum(log(diag(L)))
__device__ float g_W[KC][DD][DD];
__device__ float g_t[KC][DD];
__device__ float g_c[KC];

// ---------------- packed f32x2 helpers ----------------
__device__ __forceinline__ unsigned long long fma2(unsigned long long a,
                                                   unsigned long long b,
                                                   unsigned long long c) {
    unsigned long long d;
    asm("fma.rn.f32x2 %0, %1, %2, %3;" : "=l"(d) : "l"(a), "l"(b), "l"(c));
    return d;
}
__device__ __forceinline__ unsigned long long add2(unsigned long long a,
                                                   unsigned long long b) {
    unsigned long long d;
    asm("add.rn.f32x2 %0, %1, %2;" : "=l"(d) : "l"(a), "l"(b));
    return d;
}
__device__ __forceinline__ unsigned long long pk2(float lo, float hi) {
    unsigned long long r;
    asm("mov.b64 %0, {%1, %2};" : "=l"(r) : "f"(lo), "f"(hi));
    return r;
}
__device__ __forceinline__ float2 unpk2(unsigned long long v) {
    unsigned int lo, hi;
    asm("mov.b64 {%0, %1}, %2;" : "=r"(lo), "=r"(hi) : "l"(v));
    float2 f;
    f.x = __uint_as_float(lo);
    f.y = __uint_as_float(hi);
    return f;
}

// ---------------- cp.async helpers ----------------
__device__ __forceinline__ unsigned smem_u32(const void* p) {
    return (unsigned)__cvta_generic_to_shared(p);
}
__device__ __forceinline__ void cp16(unsigned dst, const void* src) {
    asm volatile("cp.async.cg.shared.global [%0], [%1], 16;\n"
                 :: "r"(dst), "l"(src));
}
__device__ __forceinline__ void cp_commit() {
    asm volatile("cp.async.commit_group;\n");
}
template <int N> __device__ __forceinline__ void cp_wait() {
    asm volatile("cp.async.wait_group %0;\n" :: "n"(N));
}

// ---------------- precompute v4: row-in-registers, static loops ----------
// (proven in R6: 33 us)
__global__ void __launch_bounds__(64)
gmm_precompute_kernel(const float* __restrict__ pi,
                      const float* __restrict__ mus,
                      const float* __restrict__ covs) {
    __shared__ float colbuf[2][DD];    // published column (double-buffered)
    __shared__ float rinv[DD];         // 1/L[j][j]
    __shared__ float Ls[DD][DD + 1];   // L (lower), read-only in phase 2
    __shared__ float Wsm[DD][DD + 1];  // W rows for t computation
    __shared__ float mu_s[DD];
    __shared__ float lg[DD];

    const int k = blockIdx.x;
    const int r = threadIdx.x;  // 0..63

    float a[DD];
    {
        const float4* src = (const float4*)(covs + ((size_t)k * DD + r) * DD);
#pragma unroll
        for (int i = 0; i < DD / 4; i++) {
            float4 v = src[i];
            a[4 * i] = v.x; a[4 * i + 1] = v.y;
            a[4 * i + 2] = v.z; a[4 * i + 3] = v.w;
        }
    }
    mu_s[r] = mus[k * DD + r];

    float lrow[DD];
    float d_own = 1.0f;
#pragma unroll
    for (int j = 0; j < DD; j++) {
        colbuf[j & 1][r] = a[j];
        __syncthreads();
        const float dj = colbuf[j & 1][j];
        const float rs = rsqrtf(dj);
        const float invd = rs * rs;
        lrow[j] = a[j] * rs;
        if (r == j) d_own = dj;
        const float s = a[j] * invd;
        if (r > j) {
#pragma unroll
            for (int q = j + 1; q < DD; q++)
                a[q] = fmaf(-s, colbuf[j & 1][q], a[q]);
        }
    }

    rinv[r] = rsqrtf(d_own);
    lg[r] = logf(d_own);
#pragma unroll
    for (int j = 0; j < DD; j++)
        Ls[r][j] = (r >= j) ? lrow[j] : 0.0f;
    __syncthreads();

    float w[DD];
#pragma unroll
    for (int i = 0; i < DD; i++)
        w[i] = (i == r) ? rinv[r] : 0.0f;
#pragma unroll
    for (int i = 1; i < DD; i++) {
        float acc = 0.0f;
#pragma unroll
        for (int j = 0; j < i; j++)
            acc = fmaf(Ls[i][j], w[j], acc);
        if (i > r) w[i] = -acc * rinv[i];
    }

#pragma unroll
    for (int i = 0; i < DD; i++) {
        g_W[k][i][r] = w[i];
        Wsm[i][r] = w[i];
    }
    __syncthreads();

    {
        float s = 0.0f;
#pragma unroll
        for (int j = 0; j < DD; j++)
            s = fmaf(Wsm[r][j], mu_s[j], s);
        g_t[k][r] = s;
    }
    if (r == 0) {
        float sl = 0.0f;
#pragma unroll
        for (int i = 0; i < DD; i++) sl += lg[i];
        g_c[k] = logf(pi[k]) - 32.0f * 1.8378770664093453f - 0.5f * sl;
    }
}

// ---------------- main kernel (R6 config + fused softmax) ----------------
// 128 threads/block, TWO points per thread, triangular matvec, 3 CTAs/SM.
__global__ __launch_bounds__(128, 3)
void gmm_main_kernel(const float* __restrict__ X, float* __restrict__ out,
                     int n) {
    __shared__ __align__(16) float Ws[2][DD * DD];  // 2 x 16 KB
    __shared__ __align__(16) float ts[2][DD];
    __shared__ float cs[KC];
    __shared__ float wbuf[KC][2 * 128 + 1];         // logits [k][2*tid+{0,1}]

    const int tid = threadIdx.x;
    const int p0 = (blockIdx.x * 128 + tid) * 2;
    const int ld0 = (p0 < n) ? p0 : (n - 1);
    const int ld1 = (p0 + 1 < n) ? (p0 + 1) : (n - 1);

    if (tid < KC) cs[tid] = g_c[tid];

    // Load both points into packed f32x2 registers (j-packing)
    unsigned long long pxA[DD / 2], pxB[DD / 2];
    {
        const float4* xr0 = (const float4*)(X + (size_t)ld0 * DD);
        const float4* xr1 = (const float4*)(X + (size_t)ld1 * DD);
#pragma unroll
        for (int i = 0; i < DD / 4; i++) {
            float4 v = xr0[i];
            pxA[2 * i]     = pk2(v.x, v.y);
            pxA[2 * i + 1] = pk2(v.z, v.w);
            float4 u = xr1[i];
            pxB[2 * i]     = pk2(u.x, u.y);
            pxB[2 * i + 1] = pk2(u.z, u.w);
        }
    }

    // prefetch component 0 into buffer 0
    {
        const float4* src = (const float4*)&g_W[0][0][0];
        unsigned dst = smem_u32(&Ws[0][0]);
#pragma unroll
        for (int i = 0; i < 8; i++)
            cp16(dst + (unsigned)(tid + 128 * i) * 16, src + tid + 128 * i);
        if (tid < DD / 4)
            cp16(smem_u32(&ts[0][0]) + (unsigned)tid * 16,
                 ((const float4*)&g_t[0][0]) + tid);
        cp_commit();
    }

#pragma unroll 1
    for (int k = 0; k < KC; k++) {
        const int cur = k & 1;
        if (k < KC - 1) {
            const int nxt = (k + 1) & 1;
            const float4* src = (const float4*)&g_W[k + 1][0][0];
            unsigned dst = smem_u32(&Ws[nxt][0]);
#pragma unroll
            for (int i = 0; i < 8; i++)
                cp16(dst + (unsigned)(tid + 128 * i) * 16, src + tid + 128 * i);
            if (tid < DD / 4)
                cp16(smem_u32(&ts[nxt][0]) + (unsigned)tid * 16,
                     ((const float4*)&g_t[k + 1][0]) + tid);
            cp_commit();
            cp_wait<1>();
        } else {
            cp_wait<0>();
        }
        __syncthreads();

        const float* Wc = Ws[cur];
        const float* tc = ts[cur];

        float mahaA = 0.0f, mahaB = 0.0f;
        // rows grouped by 4; group g needs cols [0, 4g+4) — triangular W
#pragma unroll
        for (int g = 0; g < DD / 4; g++) {
#pragma unroll
            for (int r = 0; r < 4; r++) {
                const int i = 4 * g + r;
                unsigned long long a0 = 0ull, a1 = 0ull;
                unsigned long long b0 = 0ull, b1 = 0ull;
                const ulonglong2* wr = (const ulonglong2*)(Wc + i * DD);
#pragma unroll
                for (int j = 0; j <= g; j++) {
                    ulonglong2 w2 = wr[j];
                    a0 = fma2(w2.x, pxA[2 * j], a0);
                    a1 = fma2(w2.y, pxA[2 * j + 1], a1);
                    b0 = fma2(w2.x, pxB[2 * j], b0);
                    b1 = fma2(w2.y, pxB[2 * j + 1], b1);
                }
                const float ti = tc[i];
                float2 a = unpk2(add2(a0, a1));
                float da = (a.x + a.y) - ti;
                mahaA = fmaf(da, da, mahaA);
                float2 b = unpk2(add2(b0, b1));
                float db = (b.x + b.y) - ti;
                mahaB = fmaf(db, db, mahaB);
            }
        }
        wbuf[k][2 * tid]     = cs[k] - 0.5f * mahaA;
        wbuf[k][2 * tid + 1] = cs[k] - 0.5f * mahaB;
        __syncthreads();
    }

    // ---- fused softmax over components (both points) ----
    if (p0 < n) {
#pragma unroll
        for (int pt = 0; pt < 2; pt++) {
            const int p = p0 + pt;
            if (p >= n) break;
            float w[KC];
            float m = -INFINITY;
#pragma unroll
            for (int k = 0; k < KC; k++) {
                w[k] = wbuf[k][2 * tid + pt];
                m = fmaxf(m, w[k]);
            }
            float s = 0.0f;
#pragma unroll
            for (int k = 0; k < KC; k++) {
                w[k] = __expf(w[k] - m);
                s += w[k];
            }
            const float inv = 1.0f / s;
            float4* orow = (float4*)(out + (size_t)p * KC);
#pragma unroll
            for (int q = 0; q < KC / 4; q++)
                orow[q] = make_float4(w[4 * q] * inv, w[4 * q + 1] * inv,
                                      w[4 * q + 2] * inv, w[4 * q + 3] * inv);
        }
    }
}

extern "C" void kernel_launch(void* const* d_in, const int* in_sizes, int n_in,
                              void* d_out, int out_size) {
    const float* X    = (const float*)d_in[0];  // [N, 64]
    const float* pi   = (const float*)d_in[1];  // [16]
    const float* mus  = (const float*)d_in[2];  // [16, 64]
    const float* covs = (const float*)d_in[3];  // [16, 64, 64]
    float* out = (float*)d_out;                 // [N, 16]

    const int n = in_sizes[0] / DD;

    gmm_precompute_kernel<<<KC, DD>>>(pi, mus, covs);
    const int pts_per_block = 256;  // 128 threads x 2 points
    gmm_main_kernel<<<(n + pts_per_block - 1) / pts_per_block, 128>>>(X, out, n);
}

// round 10
// speedup vs baseline: 2.2485x; 1.6253x over previous
#include <cuda_runtime.h>
#include <cuda_bf16.h>
#include <math.h>

#define KC 16
#define DD 64
#define TILE_M 128
#define XPAD 72   // bf16 per row (64 + 8 pad) -> 144B rows, conflict-free ldmatrix

// ---- smem offsets (bytes) ----
#define XH_OFF 0
#define XL_OFF 18432
#define WB_OFF 36864           // 2 bufs x 18432 (hi 9216 + lo 9216)
#define WBUF_BYTES 18432
#define TS_OFF 73728           // t[16][64] fp32
#define CS_OFF 77824           // c[16]
#define LOG_OFF 77888          // maha[16][132] fp32
#define LOG_STRIDE 132
#define SMEM_TOTAL (LOG_OFF + KC * LOG_STRIDE * 4)   // 86336

// Precomputed per-component data
__device__ float g_t[KC][DD];
__device__ float g_c[KC];
// W = L^{-1} split bf16 hi/lo, padded rows: [comp][split][row i][XPAD]
__device__ __align__(16) __nv_bfloat16 g_Wb16[KC][2][DD][XPAD];

// ---------------- helpers ----------------
__device__ __forceinline__ unsigned smem_u32(const void* p) {
    return (unsigned)__cvta_generic_to_shared(p);
}
__device__ __forceinline__ void cp16(unsigned dst, const void* src) {
    asm volatile("cp.async.cg.shared.global [%0], [%1], 16;\n" :: "r"(dst), "l"(src));
}
__device__ __forceinline__ void cp_commit() {
    asm volatile("cp.async.commit_group;\n");
}
template <int N> __device__ __forceinline__ void cp_wait() {
    asm volatile("cp.async.wait_group %0;\n" :: "n"(N));
}
__device__ __forceinline__ void ldmx4(unsigned& r0, unsigned& r1, unsigned& r2,
                                      unsigned& r3, unsigned addr) {
    asm volatile("ldmatrix.sync.aligned.m8n8.x4.shared.b16 {%0,%1,%2,%3}, [%4];"
                 : "=r"(r0), "=r"(r1), "=r"(r2), "=r"(r3) : "r"(addr));
}
__device__ __forceinline__ void ldmx2(unsigned& r0, unsigned& r1, unsigned addr) {
    asm volatile("ldmatrix.sync.aligned.m8n8.x2.shared.b16 {%0,%1}, [%2];"
                 : "=r"(r0), "=r"(r1) : "r"(addr));
}
__device__ __forceinline__ void mma_bf16(float* d, const unsigned* a,
                                         const unsigned* b) {
    asm volatile(
        "mma.sync.aligned.m16n8k16.row.col.f32.bf16.bf16.f32 "
        "{%0,%1,%2,%3}, {%4,%5,%6,%7}, {%8,%9}, {%0,%1,%2,%3};"
        : "+f"(d[0]), "+f"(d[1]), "+f"(d[2]), "+f"(d[3])
        : "r"(a[0]), "r"(a[1]), "r"(a[2]), "r"(a[3]), "r"(b[0]), "r"(b[1]));
}

// ---------------- precompute v4 (proven) + padded bf16-split W ----------
__global__ void __launch_bounds__(64)
gmm_precompute_kernel(const float* __restrict__ pi,
                      const float* __restrict__ mus,
                      const float* __restrict__ covs) {
    __shared__ float colbuf[2][DD];
    __shared__ float rinv[DD];
    __shared__ float Ls[DD][DD + 1];
    __shared__ float Wsm[DD][DD + 1];
    __shared__ float mu_s[DD];
    __shared__ float lg[DD];

    const int k = blockIdx.x;
    const int r = threadIdx.x;  // 0..63

    float a[DD];
    {
        const float4* src = (const float4*)(covs + ((size_t)k * DD + r) * DD);
#pragma unroll
        for (int i = 0; i < DD / 4; i++) {
            float4 v = src[i];
            a[4 * i] = v.x; a[4 * i + 1] = v.y;
            a[4 * i + 2] = v.z; a[4 * i + 3] = v.w;
        }
    }
    mu_s[r] = mus[k * DD + r];

    float lrow[DD];
    float d_own = 1.0f;
#pragma unroll
    for (int j = 0; j < DD; j++) {
        colbuf[j & 1][r] = a[j];
        __syncthreads();
        const float dj = colbuf[j & 1][j];
        const float rs = rsqrtf(dj);
        const float invd = rs * rs;
        lrow[j] = a[j] * rs;
        if (r == j) d_own = dj;
        const float s = a[j] * invd;
        if (r > j) {
#pragma unroll
            for (int q = j + 1; q < DD; q++)
                a[q] = fmaf(-s, colbuf[j & 1][q], a[q]);
        }
    }

    rinv[r] = rsqrtf(d_own);
    lg[r] = logf(d_own);
#pragma unroll
    for (int j = 0; j < DD; j++)
        Ls[r][j] = (r >= j) ? lrow[j] : 0.0f;
    __syncthreads();

    // thread r computes W column r
    float w[DD];
#pragma unroll
    for (int i = 0; i < DD; i++)
        w[i] = (i == r) ? rinv[r] : 0.0f;
#pragma unroll
    for (int i = 1; i < DD; i++) {
        float acc = 0.0f;
#pragma unroll
        for (int j = 0; j < i; j++)
            acc = fmaf(Ls[i][j], w[j], acc);
        if (i > r) w[i] = -acc * rinv[i];
    }

    // Emit bf16 hi/lo in padded B layout: g_Wb16[k][s][i][col=r]
#pragma unroll
    for (int i = 0; i < DD; i++) {
        float wv = w[i];
        __nv_bfloat16 h = __float2bfloat16_rn(wv);
        __nv_bfloat16 l = __float2bfloat16_rn(wv - __bfloat162float(h));
        g_Wb16[k][0][i][r] = h;
        g_Wb16[k][1][i][r] = l;
        Wsm[i][r] = wv;
    }
    // zero the pad columns (r < 8 handles pad col 64+r for all rows)
    if (r < XPAD - DD) {
#pragma unroll
        for (int i = 0; i < DD; i++) {
            g_Wb16[k][0][i][DD + r] = __float2bfloat16_rn(0.0f);
            g_Wb16[k][1][i][DD + r] = __float2bfloat16_rn(0.0f);
        }
    }
    __syncthreads();

    {
        float s = 0.0f;
#pragma unroll
        for (int j = 0; j < DD; j++)
            s = fmaf(Wsm[r][j], mu_s[j], s);
        g_t[k][r] = s;
    }
    if (r == 0) {
        float sl = 0.0f;
#pragma unroll
        for (int i = 0; i < DD; i++) sl += lg[i];
        g_c[k] = logf(pi[k]) - 32.0f * 1.8378770664093453f - 0.5f * sl;
    }
}

// ---------------- main kernel: warp-MMA bf16-split GEMM ----------------
// 128 threads = 4 warps; tile of 128 points; warp w owns points [32w,32w+32).
// A (X) fragments live in registers across all 16 components.
__global__ void __launch_bounds__(128)
gmm_main_kernel(const float* __restrict__ X, float* __restrict__ out, int n) {
    extern __shared__ __align__(16) char smem[];
    const int tid = threadIdx.x;
    const int warp = tid >> 5;
    const int lane = tid & 31;
    const int tile0 = blockIdx.x * TILE_M;

    // ---- load + split X row tid into padded SMEM (hi/lo) ----
    {
        const int gp = (tile0 + tid < n) ? (tile0 + tid) : (n - 1);
        const float4* xr = (const float4*)(X + (size_t)gp * DD);
        char* xh = smem + XH_OFF + tid * (XPAD * 2);
        char* xl = smem + XL_OFF + tid * (XPAD * 2);
#pragma unroll
        for (int i = 0; i < DD / 4; i++) {
            float4 v = xr[i];
            float vs[4] = {v.x, v.y, v.z, v.w};
#pragma unroll
            for (int h2 = 0; h2 < 2; h2++) {
                float x0 = vs[2 * h2], x1 = vs[2 * h2 + 1];
                __nv_bfloat162 hp, lp;
                hp.x = __float2bfloat16_rn(x0);
                hp.y = __float2bfloat16_rn(x1);
                lp.x = __float2bfloat16_rn(x0 - __bfloat162float(hp.x));
                lp.y = __float2bfloat16_rn(x1 - __bfloat162float(hp.y));
                *(__nv_bfloat162*)(xh + (4 * i + 2 * h2) * 2) = hp;
                *(__nv_bfloat162*)(xl + (4 * i + 2 * h2) * 2) = lp;
            }
        }
        // zero pad cols (8 bf16 = 16B)
        *(float4*)(xh + DD * 2) = make_float4(0.f, 0.f, 0.f, 0.f);
        *(float4*)(xl + DD * 2) = make_float4(0.f, 0.f, 0.f, 0.f);
    }

    // ---- prefetch W0 into buffer 0 ----
    {
        const float4* src = (const float4*)&g_Wb16[0][0][0][0];
        unsigned dst = smem_u32(smem + WB_OFF);
#pragma unroll
        for (int i = 0; i < 9; i++)
            cp16(dst + (unsigned)(tid + 128 * i) * 16, src + tid + 128 * i);
        cp_commit();
    }

    // ---- t and c tables ----
    for (int idx = tid; idx < KC * DD; idx += 128)
        ((float*)(smem + TS_OFF))[idx] = ((const float*)g_t)[idx];
    if (tid < KC) ((float*)(smem + CS_OFF))[tid] = g_c[tid];
    __syncthreads();   // X visible for ldmatrix

    // ---- load A fragments (X hi/lo) into registers, reused for all comps ----
    unsigned Ah[2][4][4], Al[2][4][4];
    {
        const int rbase = 32 * warp + (lane & 7) + ((lane >> 3) & 1) * 8;
        const int cbase = ((lane >> 4) & 1) * 8;
#pragma unroll
        for (int mt = 0; mt < 2; mt++) {
#pragma unroll
            for (int kt = 0; kt < 4; kt++) {
                unsigned off = (unsigned)(rbase + 16 * mt) * (XPAD * 2)
                             + (unsigned)(16 * kt + cbase) * 2;
                unsigned ah = smem_u32(smem + XH_OFF) + off;
                unsigned al = smem_u32(smem + XL_OFF) + off;
                ldmx4(Ah[mt][kt][0], Ah[mt][kt][1], Ah[mt][kt][2], Ah[mt][kt][3], ah);
                ldmx4(Al[mt][kt][0], Al[mt][kt][1], Al[mt][kt][2], Al[mt][kt][3], al);
            }
        }
    }

    float* logp = (float*)(smem + LOG_OFF);

#pragma unroll 1
    for (int k = 0; k < KC; k++) {
        const int buf = k & 1;
        cp_wait<0>();
        __syncthreads();   // W k visible to all; prev iter's reads done

        if (k < KC - 1) {  // prefetch W k+1 into the other buffer
            const float4* src = (const float4*)&g_Wb16[k + 1][0][0][0];
            unsigned dst = smem_u32(smem + WB_OFF) + (unsigned)(buf ^ 1) * WBUF_BYTES;
#pragma unroll
            for (int i = 0; i < 9; i++)
                cp16(dst + (unsigned)(tid + 128 * i) * 16, src + tid + 128 * i);
            cp_commit();
        }

        const unsigned wb_hi = smem_u32(smem + WB_OFF) + (unsigned)buf * WBUF_BYTES;
        const unsigned wb_lo = wb_hi + 9216u;
        const unsigned brow = (unsigned)(lane & 7) * (XPAD * 2);
        const unsigned bcol = (unsigned)(((lane >> 3) & 1) * 8) * 2;

        float D[2][8][4];
#pragma unroll
        for (int mt = 0; mt < 2; mt++)
#pragma unroll
            for (int nt = 0; nt < 8; nt++)
#pragma unroll
                for (int q = 0; q < 4; q++) D[mt][nt][q] = 0.0f;

#pragma unroll
        for (int nt = 0; nt < 8; nt++) {
            unsigned bh[4][2], bl[4][2];
#pragma unroll
            for (int kt = 0; kt < 4; kt++) {
                unsigned off = (unsigned)(8 * nt) * (XPAD * 2) + brow
                             + (unsigned)(16 * kt) * 2 + bcol;
                ldmx2(bh[kt][0], bh[kt][1], wb_hi + off);
                ldmx2(bl[kt][0], bl[kt][1], wb_lo + off);
            }
#pragma unroll
            for (int mt = 0; mt < 2; mt++) {
#pragma unroll
                for (int kt = 0; kt < 4; kt++) {
                    mma_bf16(D[mt][nt], Ah[mt][kt], bh[kt]);
                    mma_bf16(D[mt][nt], Al[mt][kt], bh[kt]);
                    mma_bf16(D[mt][nt], Ah[mt][kt], bl[kt]);
                }
            }
        }

        // ---- epilogue: maha = sum_n (z - t)^2, reduce across lane quads ----
        const float* tk = (const float*)(smem + TS_OFF) + k * DD;
#pragma unroll
        for (int mt = 0; mt < 2; mt++) {
            float sA = 0.0f, sB = 0.0f;
#pragma unroll
            for (int nt = 0; nt < 8; nt++) {
                float2 tv = *(const float2*)(tk + 8 * nt + 2 * (lane & 3));
                float d0 = D[mt][nt][0] - tv.x;
                float d1 = D[mt][nt][1] - tv.y;
                float d2 = D[mt][nt][2] - tv.x;
                float d3 = D[mt][nt][3] - tv.y;
                sA = fmaf(d0, d0, fmaf(d1, d1, sA));
                sB = fmaf(d2, d2, fmaf(d3, d3, sB));
            }
            sA += __shfl_xor_sync(0xffffffffu, sA, 1);
            sA += __shfl_xor_sync(0xffffffffu, sA, 2);
            sB += __shfl_xor_sync(0xffffffffu, sB, 1);
            sB += __shfl_xor_sync(0xffffffffu, sB, 2);
            if ((lane & 3) == 0) {
                const int row = 32 * warp + 16 * mt + (lane >> 2);
                logp[k * LOG_STRIDE + row] = sA;
                logp[k * LOG_STRIDE + row + 8] = sB;
            }
        }
    }
    __syncthreads();

    // ---- fused softmax over components ----
    const int p = tile0 + tid;
    if (p < n) {
        const float* csp = (const float*)(smem + CS_OFF);
        float w[KC];
        float m = -INFINITY;
#pragma unroll
        for (int k = 0; k < KC; k++) {
            w[k] = csp[k] - 0.5f * logp[k * LOG_STRIDE + tid];
            m = fmaxf(m, w[k]);
        }
        float s = 0.0f;
#pragma unroll
        for (int k = 0; k < KC; k++) {
            w[k] = __expf(w[k] - m);
            s += w[k];
        }
        const float inv = 1.0f / s;
        float4* orow = (float4*)(out + (size_t)p * KC);
#pragma unroll
        for (int q = 0; q < KC / 4; q++)
            orow[q] = make_float4(w[4 * q] * inv, w[4 * q + 1] * inv,
                                  w[4 * q + 2] * inv, w[4 * q + 3] * inv);
    }
}

extern "C" void kernel_launch(void* const* d_in, const int* in_sizes, int n_in,
                              void* d_out, int out_size) {
    const float* X    = (const float*)d_in[0];  // [N, 64]
    const float* pi   = (const float*)d_in[1];  // [16]
    const float* mus  = (const float*)d_in[2];  // [16, 64]
    const float* covs = (const float*)d_in[3];  // [16, 64, 64]
    float* out = (float*)d_out;                 // [N, 16]

    const int n = in_sizes[0] / DD;

    cudaFuncSetAttribute(gmm_main_kernel,
                         cudaFuncAttributeMaxDynamicSharedMemorySize, SMEM_TOTAL);

    gmm_precompute_kernel<<<KC, DD>>>(pi, mus, covs);
    gmm_main_kernel<<<(n + TILE_M - 1) / TILE_M, 128, SMEM_TOTAL>>>(X, out, n);
}

// round 11
// speedup vs baseline: 2.6893x; 1.1961x over previous
#include <cuda_runtime.h>
#include <cuda_bf16.h>
#include <math.h>

#define KC 16
#define DD 64
#define TILE_M 128
#define XPAD 72   // bf16 per row (64 + 8 pad) -> 144B rows, conflict-free ldmatrix

// ---- smem offsets (bytes) ----
// X staging buffers are DEAD after A-fragment ldmatrix; the W double buffer
// reuses the same 36 KB region.
#define XH_OFF 0
#define XL_OFF 18432
#define WB_OFF 0               // reuses X region: buf0=[0,18432), buf1=[18432,36864)
#define WBUF_BYTES 18432
#define TS_OFF 36864           // t[16][64] fp32
#define CS_OFF 40960           // c[16]
#define LOG_OFF 41024          // maha[16][132] fp32
#define LOG_STRIDE 132
#define SMEM_TOTAL (LOG_OFF + KC * LOG_STRIDE * 4)   // 49472

// Precomputed per-component data
__device__ float g_t[KC][DD];
__device__ float g_c[KC];
// W = L^{-1} split bf16 hi/lo, padded rows: [comp][split][row i][XPAD]
__device__ __align__(16) __nv_bfloat16 g_Wb16[KC][2][DD][XPAD];

// ---------------- helpers ----------------
__device__ __forceinline__ unsigned smem_u32(const void* p) {
    return (unsigned)__cvta_generic_to_shared(p);
}
__device__ __forceinline__ void cp16(unsigned dst, const void* src) {
    asm volatile("cp.async.cg.shared.global [%0], [%1], 16;\n" :: "r"(dst), "l"(src));
}
__device__ __forceinline__ void cp_commit() {
    asm volatile("cp.async.commit_group;\n");
}
template <int N> __device__ __forceinline__ void cp_wait() {
    asm volatile("cp.async.wait_group %0;\n" :: "n"(N));
}
__device__ __forceinline__ void ldmx4(unsigned& r0, unsigned& r1, unsigned& r2,
                                      unsigned& r3, unsigned addr) {
    asm volatile("ldmatrix.sync.aligned.m8n8.x4.shared.b16 {%0,%1,%2,%3}, [%4];"
                 : "=r"(r0), "=r"(r1), "=r"(r2), "=r"(r3) : "r"(addr));
}
__device__ __forceinline__ void ldmx2(unsigned& r0, unsigned& r1, unsigned addr) {
    asm volatile("ldmatrix.sync.aligned.m8n8.x2.shared.b16 {%0,%1}, [%2];"
                 : "=r"(r0), "=r"(r1) : "r"(addr));
}
__device__ __forceinline__ void mma_bf16(float* d, const unsigned* a,
                                         const unsigned* b) {
    asm volatile(
        "mma.sync.aligned.m16n8k16.row.col.f32.bf16.bf16.f32 "
        "{%0,%1,%2,%3}, {%4,%5,%6,%7}, {%8,%9}, {%0,%1,%2,%3};"
        : "+f"(d[0]), "+f"(d[1]), "+f"(d[2]), "+f"(d[3])
        : "r"(a[0]), "r"(a[1]), "r"(a[2]), "r"(a[3]), "r"(b[0]), "r"(b[1]));
}

// ---------------- precompute v4 (proven) + padded bf16-split W ----------
__global__ void __launch_bounds__(64)
gmm_precompute_kernel(const float* __restrict__ pi,
                      const float* __restrict__ mus,
                      const float* __restrict__ covs) {
    __shared__ float colbuf[2][DD];
    __shared__ float rinv[DD];
    __shared__ float Ls[DD][DD + 1];
    __shared__ float Wsm[DD][DD + 1];
    __shared__ float mu_s[DD];
    __shared__ float lg[DD];

    const int k = blockIdx.x;
    const int r = threadIdx.x;  // 0..63

    float a[DD];
    {
        const float4* src = (const float4*)(covs + ((size_t)k * DD + r) * DD);
#pragma unroll
        for (int i = 0; i < DD / 4; i++) {
            float4 v = src[i];
            a[4 * i] = v.x; a[4 * i + 1] = v.y;
            a[4 * i + 2] = v.z; a[4 * i + 3] = v.w;
        }
    }
    mu_s[r] = mus[k * DD + r];

    float lrow[DD];
    float d_own = 1.0f;
#pragma unroll
    for (int j = 0; j < DD; j++) {
        colbuf[j & 1][r] = a[j];
        __syncthreads();
        const float dj = colbuf[j & 1][j];
        const float rs = rsqrtf(dj);
        const float invd = rs * rs;
        lrow[j] = a[j] * rs;
        if (r == j) d_own = dj;
        const float s = a[j] * invd;
        if (r > j) {
#pragma unroll
            for (int q = j + 1; q < DD; q++)
                a[q] = fmaf(-s, colbuf[j & 1][q], a[q]);
        }
    }

    rinv[r] = rsqrtf(d_own);
    lg[r] = logf(d_own);
#pragma unroll
    for (int j = 0; j < DD; j++)
        Ls[r][j] = (r >= j) ? lrow[j] : 0.0f;
    __syncthreads();

    // thread r computes W column r
    float w[DD];
#pragma unroll
    for (int i = 0; i < DD; i++)
        w[i] = (i == r) ? rinv[r] : 0.0f;
#pragma unroll
    for (int i = 1; i < DD; i++) {
        float acc = 0.0f;
#pragma unroll
        for (int j = 0; j < i; j++)
            acc = fmaf(Ls[i][j], w[j], acc);
        if (i > r) w[i] = -acc * rinv[i];
    }

    // Emit bf16 hi/lo in padded B layout: g_Wb16[k][s][i][col=r]
#pragma unroll
    for (int i = 0; i < DD; i++) {
        float wv = w[i];
        __nv_bfloat16 h = __float2bfloat16_rn(wv);
        __nv_bfloat16 l = __float2bfloat16_rn(wv - __bfloat162float(h));
        g_Wb16[k][0][i][r] = h;
        g_Wb16[k][1][i][r] = l;
        Wsm[i][r] = wv;
    }
    // zero the pad columns
    if (r < XPAD - DD) {
#pragma unroll
        for (int i = 0; i < DD; i++) {
            g_Wb16[k][0][i][DD + r] = __float2bfloat16_rn(0.0f);
            g_Wb16[k][1][i][DD + r] = __float2bfloat16_rn(0.0f);
        }
    }
    __syncthreads();

    {
        float s = 0.0f;
#pragma unroll
        for (int j = 0; j < DD; j++)
            s = fmaf(Wsm[r][j], mu_s[j], s);
        g_t[k][r] = s;
    }
    if (r == 0) {
        float sl = 0.0f;
#pragma unroll
        for (int i = 0; i < DD; i++) sl += lg[i];
        g_c[k] = logf(pi[k]) - 32.0f * 1.8378770664093453f - 0.5f * sl;
    }
}

// ---------------- main kernel: warp-MMA bf16-split GEMM ----------------
// 128 threads = 4 warps; tile of 128 points; warp w owns points [32w,32w+32).
// A (X) fragments live in registers across all 16 components; the X SMEM
// staging region is then reused as the W double buffer.
__global__ void __launch_bounds__(128)
gmm_main_kernel(const float* __restrict__ X, float* __restrict__ out, int n) {
    extern __shared__ __align__(16) char smem[];
    const int tid = threadIdx.x;
    const int warp = tid >> 5;
    const int lane = tid & 31;
    const int tile0 = blockIdx.x * TILE_M;

    // ---- load + split X row tid into padded SMEM (hi/lo) ----
    {
        const int gp = (tile0 + tid < n) ? (tile0 + tid) : (n - 1);
        const float4* xr = (const float4*)(X + (size_t)gp * DD);
        char* xh = smem + XH_OFF + tid * (XPAD * 2);
        char* xl = smem + XL_OFF + tid * (XPAD * 2);
#pragma unroll
        for (int i = 0; i < DD / 4; i++) {
            float4 v = xr[i];
            float vs[4] = {v.x, v.y, v.z, v.w};
#pragma unroll
            for (int h2 = 0; h2 < 2; h2++) {
                float x0 = vs[2 * h2], x1 = vs[2 * h2 + 1];
                __nv_bfloat162 hp, lp;
                hp.x = __float2bfloat16_rn(x0);
                hp.y = __float2bfloat16_rn(x1);
                lp.x = __float2bfloat16_rn(x0 - __bfloat162float(hp.x));
                lp.y = __float2bfloat16_rn(x1 - __bfloat162float(hp.y));
                *(__nv_bfloat162*)(xh + (4 * i + 2 * h2) * 2) = hp;
                *(__nv_bfloat162*)(xl + (4 * i + 2 * h2) * 2) = lp;
            }
        }
        // zero pad cols (8 bf16 = 16B)
        *(float4*)(xh + DD * 2) = make_float4(0.f, 0.f, 0.f, 0.f);
        *(float4*)(xl + DD * 2) = make_float4(0.f, 0.f, 0.f, 0.f);
    }

    // ---- t and c tables (non-overlapping region) ----
    for (int idx = tid; idx < KC * DD; idx += 128)
        ((float*)(smem + TS_OFF))[idx] = ((const float*)g_t)[idx];
    if (tid < KC) ((float*)(smem + CS_OFF))[tid] = g_c[tid];
    __syncthreads();   // X visible for ldmatrix

    // ---- load A fragments (X hi/lo) into registers, reused for all comps ----
    unsigned Ah[2][4][4], Al[2][4][4];
    {
        const int rbase = 32 * warp + (lane & 7) + ((lane >> 3) & 1) * 8;
        const int cbase = ((lane >> 4) & 1) * 8;
#pragma unroll
        for (int mt = 0; mt < 2; mt++) {
#pragma unroll
            for (int kt = 0; kt < 4; kt++) {
                unsigned off = (unsigned)(rbase + 16 * mt) * (XPAD * 2)
                             + (unsigned)(16 * kt + cbase) * 2;
                unsigned ah = smem_u32(smem + XH_OFF) + off;
                unsigned al = smem_u32(smem + XL_OFF) + off;
                ldmx4(Ah[mt][kt][0], Ah[mt][kt][1], Ah[mt][kt][2], Ah[mt][kt][3], ah);
                ldmx4(Al[mt][kt][0], Al[mt][kt][1], Al[mt][kt][2], Al[mt][kt][3], al);
            }
        }
    }
    __syncthreads();   // ALL warps done reading X -> region reusable for W

    // ---- prefetch W0 into buffer 0 (overwrites dead X region) ----
    {
        const float4* src = (const float4*)&g_Wb16[0][0][0][0];
        unsigned dst = smem_u32(smem + WB_OFF);
#pragma unroll
        for (int i = 0; i < 9; i++)
            cp16(dst + (unsigned)(tid + 128 * i) * 16, src + tid + 128 * i);
        cp_commit();
    }

    float* logp = (float*)(smem + LOG_OFF);

#pragma unroll 1
    for (int k = 0; k < KC; k++) {
        const int buf = k & 1;
        cp_wait<0>();
        __syncthreads();   // W k visible to all; prev iter's reads done

        if (k < KC - 1) {  // prefetch W k+1 into the other buffer
            const float4* src = (const float4*)&g_Wb16[k + 1][0][0][0];
            unsigned dst = smem_u32(smem + WB_OFF) + (unsigned)(buf ^ 1) * WBUF_BYTES;
#pragma unroll
            for (int i = 0; i < 9; i++)
                cp16(dst + (unsigned)(tid + 128 * i) * 16, src + tid + 128 * i);
            cp_commit();
        }

        const unsigned wb_hi = smem_u32(smem + WB_OFF) + (unsigned)buf * WBUF_BYTES;
        const unsigned wb_lo = wb_hi + 9216u;
        const unsigned brow = (unsigned)(lane & 7) * (XPAD * 2);
        const unsigned bcol = (unsigned)(((lane >> 3) & 1) * 8) * 2;
        const float* tk = (const float*)(smem + TS_OFF) + k * DD;

        float sA0 = 0.0f, sB0 = 0.0f, sA1 = 0.0f, sB1 = 0.0f;

#pragma unroll
        for (int nt = 0; nt < 8; nt++) {
            unsigned bh[4][2], bl[4][2];
#pragma unroll
            for (int kt = 0; kt < 4; kt++) {
                unsigned off = (unsigned)(8 * nt) * (XPAD * 2) + brow
                             + (unsigned)(16 * kt) * 2 + bcol;
                ldmx2(bh[kt][0], bh[kt][1], wb_hi + off);
                ldmx2(bl[kt][0], bl[kt][1], wb_lo + off);
            }
            const float2 tv = *(const float2*)(tk + 8 * nt + 2 * (lane & 3));
#pragma unroll
            for (int mt = 0; mt < 2; mt++) {
                float D[4] = {0.0f, 0.0f, 0.0f, 0.0f};
#pragma unroll
                for (int kt = 0; kt < 4; kt++) {
                    mma_bf16(D, Ah[mt][kt], bh[kt]);
                    mma_bf16(D, Al[mt][kt], bh[kt]);
                    mma_bf16(D, Ah[mt][kt], bl[kt]);
                }
                float d0 = D[0] - tv.x;
                float d1 = D[1] - tv.y;
                float d2 = D[2] - tv.x;
                float d3 = D[3] - tv.y;
                if (mt == 0) {
                    sA0 = fmaf(d0, d0, fmaf(d1, d1, sA0));
                    sB0 = fmaf(d2, d2, fmaf(d3, d3, sB0));
                } else {
                    sA1 = fmaf(d0, d0, fmaf(d1, d1, sA1));
                    sB1 = fmaf(d2, d2, fmaf(d3, d3, sB1));
                }
            }
        }

        // ---- reduce across lane quads, write logs ----
        sA0 += __shfl_xor_sync(0xffffffffu, sA0, 1);
        sA0 += __shfl_xor_sync(0xffffffffu, sA0, 2);
        sB0 += __shfl_xor_sync(0xffffffffu, sB0, 1);
        sB0 += __shfl_xor_sync(0xffffffffu, sB0, 2);
        sA1 += __shfl_xor_sync(0xffffffffu, sA1, 1);
        sA1 += __shfl_xor_sync(0xffffffffu, sA1, 2);
        sB1 += __shfl_xor_sync(0xffffffffu, sB1, 1);
        sB1 += __shfl_xor_sync(0xffffffffu, sB1, 2);
        if ((lane & 3) == 0) {
            const int row = 32 * warp + (lane >> 2);
            logp[k * LOG_STRIDE + row] = sA0;
            logp[k * LOG_STRIDE + row + 8] = sB0;
            logp[k * LOG_STRIDE + row + 16] = sA1;
            logp[k * LOG_STRIDE + row + 24] = sB1;
        }
    }
    __syncthreads();

    // ---- fused softmax over components ----
    const int p = tile0 + tid;
    if (p < n) {
        const float* csp = (const float*)(smem + CS_OFF);
        float w[KC];
        float m = -INFINITY;
#pragma unroll
        for (int k = 0; k < KC; k++) {
            w[k] = csp[k] - 0.5f * logp[k * LOG_STRIDE + tid];
            m = fmaxf(m, w[k]);
        }
        float s = 0.0f;
#pragma unroll
        for (int k = 0; k < KC; k++) {
            w[k] = __expf(w[k] - m);
            s += w[k];
        }
        const float inv = 1.0f / s;
        float4* orow = (float4*)(out + (size_t)p * KC);
#pragma unroll
        for (int q = 0; q < KC / 4; q++)
            orow[q] = make_float4(w[4 * q] * inv, w[4 * q + 1] * inv,
                                  w[4 * q + 2] * inv, w[4 * q + 3] * inv);
    }
}

extern "C" void kernel_launch(void* const* d_in, const int* in_sizes, int n_in,
                              void* d_out, int out_size) {
    const float* X    = (const float*)d_in[0];  // [N, 64]
    const float* pi   = (const float*)d_in[1];  // [16]
    const float* mus  = (const float*)d_in[2];  // [16, 64]
    const float* covs = (const float*)d_in[3];  // [16, 64, 64]
    float* out = (float*)d_out;                 // [N, 16]

    const int n = in_sizes[0] / DD;

    cudaFuncSetAttribute(gmm_main_kernel,
                         cudaFuncAttributeMaxDynamicSharedMemorySize, SMEM_TOTAL);

    gmm_precompute_kernel<<<KC, DD>>>(pi, mus, covs);
    gmm_main_kernel<<<(n + TILE_M - 1) / TILE_M, 128, SMEM_TOTAL>>>(X, out, n);
}

// round 12
// speedup vs baseline: 3.5798x; 1.3311x over previous
#include <cuda_runtime.h>
#include <cuda_bf16.h>
#include <math.h>

#define KC 16
#define DD 64
#define TILE_M 128
#define XPAD 72   // bf16 per row (64 + 8 pad) -> 144B rows, conflict-free ldmatrix

// ---- smem offsets (bytes) ----
// X staging buffers are DEAD after A-fragment ldmatrix; the W double buffer
// reuses the same 36 KB region.
#define XH_OFF 0
#define XL_OFF 18432
#define WB_OFF 0               // reuses X region: buf0=[0,18432), buf1=[18432,36864)
#define WBUF_BYTES 18432
#define TS_OFF 36864           // t[16][64] fp32
#define CS_OFF 40960           // c[16]
#define LOG_OFF 41024          // maha[16][132] fp32
#define LOG_STRIDE 132
#define SMEM_TOTAL (LOG_OFF + KC * LOG_STRIDE * 4)   // 49472

// Precomputed per-component data
__device__ float g_t[KC][DD];
__device__ float g_c[KC];
// W = L^{-1} split bf16 hi/lo, padded rows: [comp][split][row i][XPAD]
__device__ __align__(16) __nv_bfloat16 g_Wb16[KC][2][DD][XPAD];

// ---------------- helpers ----------------
__device__ __forceinline__ unsigned smem_u32(const void* p) {
    return (unsigned)__cvta_generic_to_shared(p);
}
__device__ __forceinline__ void cp16(unsigned dst, const void* src) {
    asm volatile("cp.async.cg.shared.global [%0], [%1], 16;\n" :: "r"(dst), "l"(src));
}
__device__ __forceinline__ void cp_commit() {
    asm volatile("cp.async.commit_group;\n");
}
template <int N> __device__ __forceinline__ void cp_wait() {
    asm volatile("cp.async.wait_group %0;\n" :: "n"(N));
}
__device__ __forceinline__ void ldmx4(unsigned& r0, unsigned& r1, unsigned& r2,
                                      unsigned& r3, unsigned addr) {
    asm volatile("ldmatrix.sync.aligned.m8n8.x4.shared.b16 {%0,%1,%2,%3}, [%4];"
                 : "=r"(r0), "=r"(r1), "=r"(r2), "=r"(r3) : "r"(addr));
}
__device__ __forceinline__ void ldmx2(unsigned& r0, unsigned& r1, unsigned addr) {
    asm volatile("ldmatrix.sync.aligned.m8n8.x2.shared.b16 {%0,%1}, [%2];"
                 : "=r"(r0), "=r"(r1) : "r"(addr));
}
__device__ __forceinline__ void mma_bf16(float* d, const unsigned* a,
                                         const unsigned* b) {
    asm volatile(
        "mma.sync.aligned.m16n8k16.row.col.f32.bf16.bf16.f32 "
        "{%0,%1,%2,%3}, {%4,%5,%6,%7}, {%8,%9}, {%0,%1,%2,%3};"
        : "+f"(d[0]), "+f"(d[1]), "+f"(d[2]), "+f"(d[3])
        : "r"(a[0]), "r"(a[1]), "r"(a[2]), "r"(a[3]), "r"(b[0]), "r"(b[1]));
}

// ---------------- precompute v4 (proven) + padded bf16-split W ----------
__global__ void __launch_bounds__(64)
gmm_precompute_kernel(const float* __restrict__ pi,
                      const float* __restrict__ mus,
                      const float* __restrict__ covs) {
    __shared__ float colbuf[2][DD];
    __shared__ float rinv[DD];
    __shared__ float Ls[DD][DD + 1];
    __shared__ float Wsm[DD][DD + 1];
    __shared__ float mu_s[DD];
    __shared__ float lg[DD];

    const int k = blockIdx.x;
    const int r = threadIdx.x;  // 0..63

    float a[DD];
    {
        const float4* src = (const float4*)(covs + ((size_t)k * DD + r) * DD);
#pragma unroll
        for (int i = 0; i < DD / 4; i++) {
            float4 v = src[i];
            a[4 * i] = v.x; a[4 * i + 1] = v.y;
            a[4 * i + 2] = v.z; a[4 * i + 3] = v.w;
        }
    }
    mu_s[r] = mus[k * DD + r];

    float lrow[DD];
    float d_own = 1.0f;
#pragma unroll
    for (int j = 0; j < DD; j++) {
        colbuf[j & 1][r] = a[j];
        __syncthreads();
        const float dj = colbuf[j & 1][j];
        const float rs = rsqrtf(dj);
        const float invd = rs * rs;
        lrow[j] = a[j] * rs;
        if (r == j) d_own = dj;
        const float s = a[j] * invd;
        if (r > j) {
#pragma unroll
            for (int q = j + 1; q < DD; q++)
                a[q] = fmaf(-s, colbuf[j & 1][q], a[q]);
        }
    }

    rinv[r] = rsqrtf(d_own);
    lg[r] = logf(d_own);
#pragma unroll
    for (int j = 0; j < DD; j++)
        Ls[r][j] = (r >= j) ? lrow[j] : 0.0f;
    __syncthreads();

    // thread r computes W column r
    float w[DD];
#pragma unroll
    for (int i = 0; i < DD; i++)
        w[i] = (i == r) ? rinv[r] : 0.0f;
#pragma unroll
    for (int i = 1; i < DD; i++) {
        float acc = 0.0f;
#pragma unroll
        for (int j = 0; j < i; j++)
            acc = fmaf(Ls[i][j], w[j], acc);
        if (i > r) w[i] = -acc * rinv[i];
    }

    // Emit bf16 hi/lo in padded B layout: g_Wb16[k][s][i][col=r]
#pragma unroll
    for (int i = 0; i < DD; i++) {
        float wv = w[i];
        __nv_bfloat16 h = __float2bfloat16_rn(wv);
        __nv_bfloat16 l = __float2bfloat16_rn(wv - __bfloat162float(h));
        g_Wb16[k][0][i][r] = h;
        g_Wb16[k][1][i][r] = l;
        Wsm[i][r] = wv;
    }
    // zero the pad columns
    if (r < XPAD - DD) {
#pragma unroll
        for (int i = 0; i < DD; i++) {
            g_Wb16[k][0][i][DD + r] = __float2bfloat16_rn(0.0f);
            g_Wb16[k][1][i][DD + r] = __float2bfloat16_rn(0.0f);
        }
    }
    __syncthreads();

    {
        float s = 0.0f;
#pragma unroll
        for (int j = 0; j < DD; j++)
            s = fmaf(Wsm[r][j], mu_s[j], s);
        g_t[k][r] = s;
    }
    if (r == 0) {
        float sl = 0.0f;
#pragma unroll
        for (int i = 0; i < DD; i++) sl += lg[i];
        g_c[k] = logf(pi[k]) - 32.0f * 1.8378770664093453f - 0.5f * sl;
    }
}

// ---------------- main kernel: warp-MMA bf16-split triangular GEMM -------
// 128 threads = 4 warps; tile of 128 points; warp w owns points [32w,32w+32).
// A (X) fragments live in registers across all 16 components; X SMEM region
// is reused as the W double buffer. W is lower triangular: output n-tile nt
// only needs K-blocks kt <= nt/2 (the rest are exact zeros) -> 20/32 blocks.
__global__ void __launch_bounds__(128)
gmm_main_kernel(const float* __restrict__ X, float* __restrict__ out, int n) {
    extern __shared__ __align__(16) char smem[];
    const int tid = threadIdx.x;
    const int warp = tid >> 5;
    const int lane = tid & 31;
    const int tile0 = blockIdx.x * TILE_M;

    // ---- load + split X row tid into padded SMEM (hi/lo) ----
    {
        const int gp = (tile0 + tid < n) ? (tile0 + tid) : (n - 1);
        const float4* xr = (const float4*)(X + (size_t)gp * DD);
        char* xh = smem + XH_OFF + tid * (XPAD * 2);
        char* xl = smem + XL_OFF + tid * (XPAD * 2);
#pragma unroll
        for (int i = 0; i < DD / 4; i++) {
            float4 v = xr[i];
            float vs[4] = {v.x, v.y, v.z, v.w};
#pragma unroll
            for (int h2 = 0; h2 < 2; h2++) {
                float x0 = vs[2 * h2], x1 = vs[2 * h2 + 1];
                __nv_bfloat162 hp, lp;
                hp.x = __float2bfloat16_rn(x0);
                hp.y = __float2bfloat16_rn(x1);
                lp.x = __float2bfloat16_rn(x0 - __bfloat162float(hp.x));
                lp.y = __float2bfloat16_rn(x1 - __bfloat162float(hp.y));
                *(__nv_bfloat162*)(xh + (4 * i + 2 * h2) * 2) = hp;
                *(__nv_bfloat162*)(xl + (4 * i + 2 * h2) * 2) = lp;
            }
        }
        // zero pad cols (8 bf16 = 16B)
        *(float4*)(xh + DD * 2) = make_float4(0.f, 0.f, 0.f, 0.f);
        *(float4*)(xl + DD * 2) = make_float4(0.f, 0.f, 0.f, 0.f);
    }

    // ---- t and c tables (non-overlapping region) ----
    for (int idx = tid; idx < KC * DD; idx += 128)
        ((float*)(smem + TS_OFF))[idx] = ((const float*)g_t)[idx];
    if (tid < KC) ((float*)(smem + CS_OFF))[tid] = g_c[tid];
    __syncthreads();   // X visible for ldmatrix

    // ---- load A fragments (X hi/lo) into registers, reused for all comps ----
    unsigned Ah[2][4][4], Al[2][4][4];
    {
        const int rbase = 32 * warp + (lane & 7) + ((lane >> 3) & 1) * 8;
        const int cbase = ((lane >> 4) & 1) * 8;
#pragma unroll
        for (int mt = 0; mt < 2; mt++) {
#pragma unroll
            for (int kt = 0; kt < 4; kt++) {
                unsigned off = (unsigned)(rbase + 16 * mt) * (XPAD * 2)
                             + (unsigned)(16 * kt + cbase) * 2;
                unsigned ah = smem_u32(smem + XH_OFF) + off;
                unsigned al = smem_u32(smem + XL_OFF) + off;
                ldmx4(Ah[mt][kt][0], Ah[mt][kt][1], Ah[mt][kt][2], Ah[mt][kt][3], ah);
                ldmx4(Al[mt][kt][0], Al[mt][kt][1], Al[mt][kt][2], Al[mt][kt][3], al);
            }
        }
    }
    __syncthreads();   // ALL warps done reading X -> region reusable for W

    // ---- prefetch W0 into buffer 0 (overwrites dead X region) ----
    {
        const float4* src = (const float4*)&g_Wb16[0][0][0][0];
        unsigned dst = smem_u32(smem + WB_OFF);
#pragma unroll
        for (int i = 0; i < 9; i++)
            cp16(dst + (unsigned)(tid + 128 * i) * 16, src + tid + 128 * i);
        cp_commit();
    }

    float* logp = (float*)(smem + LOG_OFF);

#pragma unroll 1
    for (int k = 0; k < KC; k++) {
        const int buf = k & 1;
        cp_wait<0>();
        __syncthreads();   // W k visible to all; prev iter's reads done

        if (k < KC - 1) {  // prefetch W k+1 into the other buffer
            const float4* src = (const float4*)&g_Wb16[k + 1][0][0][0];
            unsigned dst = smem_u32(smem + WB_OFF) + (unsigned)(buf ^ 1) * WBUF_BYTES;
#pragma unroll
            for (int i = 0; i < 9; i++)
                cp16(dst + (unsigned)(tid + 128 * i) * 16, src + tid + 128 * i);
            cp_commit();
        }

        const unsigned wb_hi = smem_u32(smem + WB_OFF) + (unsigned)buf * WBUF_BYTES;
        const unsigned wb_lo = wb_hi + 9216u;
        const unsigned brow = (unsigned)(lane & 7) * (XPAD * 2);
        const unsigned bcol = (unsigned)(((lane >> 3) & 1) * 8) * 2;
        const float* tk = (const float*)(smem + TS_OFF) + k * DD;

        float sA0 = 0.0f, sB0 = 0.0f, sA1 = 0.0f, sB1 = 0.0f;

#pragma unroll
        for (int nt = 0; nt < 8; nt++) {
            // Triangular W: output dims [8nt, 8nt+8) need K cols < 8nt+8,
            // i.e. kt blocks 0..nt/2. Blocks above are exact zeros -> skip.
            const int KTN = nt / 2 + 1;   // compile-time (nt unrolled)
            unsigned bh[4][2], bl[4][2];
#pragma unroll
            for (int kt = 0; kt < KTN; kt++) {
                unsigned off = (unsigned)(8 * nt) * (XPAD * 2) + brow
                             + (unsigned)(16 * kt) * 2 + bcol;
                ldmx2(bh[kt][0], bh[kt][1], wb_hi + off);
                ldmx2(bl[kt][0], bl[kt][1], wb_lo + off);
            }
            const float2 tv = *(const float2*)(tk + 8 * nt + 2 * (lane & 3));
#pragma unroll
            for (int mt = 0; mt < 2; mt++) {
                float D[4] = {0.0f, 0.0f, 0.0f, 0.0f};
#pragma unroll
                for (int kt = 0; kt < KTN; kt++) {
                    mma_bf16(D, Ah[mt][kt], bh[kt]);
                    mma_bf16(D, Al[mt][kt], bh[kt]);
                    mma_bf16(D, Ah[mt][kt], bl[kt]);
                }
                float d0 = D[0] - tv.x;
                float d1 = D[1] - tv.y;
                float d2 = D[2] - tv.x;
                float d3 = D[3] - tv.y;
                if (mt == 0) {
                    sA0 = fmaf(d0, d0, fmaf(d1, d1, sA0));
                    sB0 = fmaf(d2, d2, fmaf(d3, d3, sB0));
                } else {
                    sA1 = fmaf(d0, d0, fmaf(d1, d1, sA1));
                    sB1 = fmaf(d2, d2, fmaf(d3, d3, sB1));
                }
            }
        }

        // ---- reduce across lane quads, write logs ----
        sA0 += __shfl_xor_sync(0xffffffffu, sA0, 1);
        sA0 += __shfl_xor_sync(0xffffffffu, sA0, 2);
        sB0 += __shfl_xor_sync(0xffffffffu, sB0, 1);
        sB0 += __shfl_xor_sync(0xffffffffu, sB0, 2);
        sA1 += __shfl_xor_sync(0xffffffffu, sA1, 1);
        sA1 += __shfl_xor_sync(0xffffffffu, sA1, 2);
        sB1 += __shfl_xor_sync(0xffffffffu, sB1, 1);
        sB1 += __shfl_xor_sync(0xffffffffu, sB1, 2);
        if ((lane & 3) == 0) {
            const int row = 32 * warp + (lane >> 2);
            logp[k * LOG_STRIDE + row] = sA0;
            logp[k * LOG_STRIDE + row + 8] = sB0;
            logp[k * LOG_STRIDE + row + 16] = sA1;
            logp[k * LOG_STRIDE + row + 24] = sB1;
        }
    }
    __syncthreads();

    // ---- fused softmax over components ----
    const int p = tile0 + tid;
    if (p < n) {
        const float* csp = (const float*)(smem + CS_OFF);
        float w[KC];
        float m = -INFINITY;
#pragma unroll
        for (int k = 0; k < KC; k++) {
            w[k] = csp[k] - 0.5f * logp[k * LOG_STRIDE + tid];
            m = fmaxf(m, w[k]);
        }
        float s = 0.0f;
#pragma unroll
        for (int k = 0; k < KC; k++) {
            w[k] = __expf(w[k] - m);
            s += w[k];
        }
        const float inv = 1.0f / s;
        float4* orow = (float4*)(out + (size_t)p * KC);
#pragma unroll
        for (int q = 0; q < KC / 4; q++)
            orow[q] = make_float4(w[4 * q] * inv, w[4 * q + 1] * inv,
                                  w[4 * q + 2] * inv, w[4 * q + 3] * inv);
    }
}

extern "C" void kernel_launch(void* const* d_in, const int* in_sizes, int n_in,
                              void* d_out, int out_size) {
    const float* X    = (const float*)d_in[0];  // [N, 64]
    const float* pi   = (const float*)d_in[1];  // [16]
    const float* mus  = (const float*)d_in[2];  // [16, 64]
    const float* covs = (const float*)d_in[3];  // [16, 64, 64]
    float* out = (float*)d_out;                 // [N, 16]

    const int n = in_sizes[0] / DD;

    cudaFuncSetAttribute(gmm_main_kernel,
                         cudaFuncAttributeMaxDynamicSharedMemorySize, SMEM_TOTAL);

    gmm_precompute_kernel<<<KC, DD>>>(pi, mus, covs);
    gmm_main_kernel<<<(n + TILE_M - 1) / TILE_M, 128, SMEM_TOTAL>>>(X, out, n);
}